// round 5
// baseline (speedup 1.0000x reference)
#include <cuda_runtime.h>

// DynamicUpsamplingFilter: out[b,c,h,w] = sum_{dy,dx} x_pad[b,c,h+dy,w+dx] * filters[b,dy*3+dx,h,w]
// x: [4,128,180,320] f32, filters: [4,9,180,320] f32, out: [4,128,180,320] f32.
//
// R5: 2 pixels per thread (float2), 32 channels per thread.
// Same L1 wavefronts/pixel as the 4-pixel version (load pattern cost is
// span-invariant), but filter regs drop 36->18 so the kernel fits
// 5 blocks/SM (51-reg cap) WITHOUT spilling -> occ ~62% vs R2's 24%.
// L1-bound: goal is to saturate the L1 pipe (was 58% at occ 24%).

constexpr int B = 4, C = 128, H = 180, W = 320;
constexpr int HW = H * W;
constexpr int WP = W / 2;            // 160 pixel-pairs per row
constexpr int CCH = 32;              // channels per thread
constexpr int NCQ = C / CCH;         // 4 channel-groups
constexpr int THREADS = 256;
constexpr int NTHREADS_TOTAL = B * NCQ * H * WP;   // 460800
constexpr int GRID = NTHREADS_TOTAL / THREADS;     // 1800

__global__ __launch_bounds__(THREADS, 5)
void duf_kernel(const float* __restrict__ x,
                const float* __restrict__ f,
                float* __restrict__ out)
{
    int idx = blockIdx.x * THREADS + threadIdx.x;

    // consecutive threads -> consecutive wp for coalescing
    int wp = idx % WP;
    int t  = idx / WP;
    int h  = t % H;
    t /= H;
    int cq = t % NCQ;
    int b  = t / NCQ;
    int w  = wp * 2;

    // ---- load 9 filter tap pairs (pixels w, w+1) into registers ----
    const float* fp = f + (size_t)b * 9 * HW + (size_t)h * W + w;
    float2 fv[9];
#pragma unroll
    for (int i = 0; i < 9; ++i)
        fv[i] = *(const float2*)(fp + (size_t)i * HW);

    // vertical boundary: zero whole tap rows
    if (h == 0) {
#pragma unroll
        for (int i = 0; i < 3; ++i) fv[i] = make_float2(0.f, 0.f);
    }
    if (h == H - 1) {
#pragma unroll
        for (int i = 6; i < 9; ++i) fv[i] = make_float2(0.f, 0.f);
    }
    // horizontal boundary: pixel 0 loses dx=-1 taps, pixel 1 loses dx=+1 taps
    if (w == 0)     { fv[0].x = 0.f; fv[3].x = 0.f; fv[6].x = 0.f; }
    if (w == W - 2) { fv[2].y = 0.f; fv[5].y = 0.f; fv[8].y = 0.f; }

    // clamped offsets (dead loads land in-bounds; their filter is zero)
    int roff[3];
    roff[0] = (h > 0)     ? -W : 0;
    roff[1] = 0;
    roff[2] = (h < H - 1) ?  W : 0;
    int offm1 = (w > 0)     ? -1 : 0;   // column w-1
    int offp2 = (w + 2 < W) ?  2 : 1;   // column w+2

    const float* xp = x   + ((size_t)b * C + cq * CCH) * HW + (size_t)h * W + w;
    float*       op = out + ((size_t)b * C + cq * CCH) * HW + (size_t)h * W + w;

    for (int c = 0; c < CCH; ++c) {
        const float* xc = xp + (size_t)c * HW;

        // 9 independent loads for this channel
        float2 m[3];
        float  vm1[3], vp2[3];
#pragma unroll
        for (int r = 0; r < 3; ++r) {
            const float* row = xc + roff[r];
            m[r]   = *(const float2*)row;     // columns w, w+1
            vm1[r] = __ldg(row + offm1);      // column w-1
            vp2[r] = __ldg(row + offp2);      // column w+2
        }

        float a0 = 0.f, a1 = 0.f;
#pragma unroll
        for (int r = 0; r < 3; ++r) {
            float2 F0 = fv[3 * r + 0];        // dx=-1 taps
            float2 F1 = fv[3 * r + 1];        // dx= 0
            float2 F2 = fv[3 * r + 2];        // dx=+1
            a0 = fmaf(vm1[r], F0.x, a0); a0 = fmaf(m[r].x, F1.x, a0); a0 = fmaf(m[r].y, F2.x, a0);
            a1 = fmaf(m[r].x, F0.y, a1); a1 = fmaf(m[r].y, F1.y, a1); a1 = fmaf(vp2[r], F2.y, a1);
        }
        *(float2*)(op + (size_t)c * HW) = make_float2(a0, a1);
    }
}

extern "C" void kernel_launch(void* const* d_in, const int* in_sizes, int n_in,
                              void* d_out, int out_size)
{
    const float* x = (const float*)d_in[0];   // [4,128,180,320]
    const float* f = (const float*)d_in[1];   // [4,9,180,320]
    float* out = (float*)d_out;               // [4,128,180,320]

    duf_kernel<<<GRID, THREADS>>>(x, f, out);
}

// round 6
// speedup vs baseline: 1.8428x; 1.8428x over previous
#include <cuda_runtime.h>

// DynamicUpsamplingFilter: out[b,c,h,w] = sum_{dy,dx} x_pad[b,c,h+dy,w+dx] * filters[b,dy*3+dx,h,w]
// x: [4,128,180,320] f32, filters: [4,9,180,320] f32, out: [4,128,180,320] f32.
//
// R6: thread owns a 4(w) x 2(h) pixel tile and 16 channels.
// The two output rows share input rows h and h+1: per channel only 4 input
// rows (4 vec + 8 halo loads) instead of 6 (6 vec + 12 halos for two
// independent rows) -> L1 wavefronts/pixel down 39% vs R2, DRAM vertical
// redundancy 3x -> 2x. Filters for both rows (18 float4) live in registers
// across the channel loop. Boundary handling stays branch-free: clamp
// addresses, zero the register-resident filter components.

constexpr int B = 4, C = 128, H = 180, W = 320;
constexpr int HW = H * W;
constexpr int WQ = W / 4;            // 80 pixel-quads per row
constexpr int HP = H / 2;            // 90 row-pairs
constexpr int CCH = 16;              // channels per thread
constexpr int NCQ = C / CCH;         // 8 channel-groups
constexpr int THREADS = 256;
constexpr int NTHREADS_TOTAL = B * NCQ * HP * WQ;  // 230400
constexpr int GRID = NTHREADS_TOTAL / THREADS;     // 900

__global__ __launch_bounds__(THREADS, 2)
void duf_kernel(const float* __restrict__ x,
                const float* __restrict__ f,
                float* __restrict__ out)
{
    int idx = blockIdx.x * THREADS + threadIdx.x;

    // consecutive threads -> consecutive wq for coalescing
    int wq = idx % WQ;
    int t  = idx / WQ;
    int hp = t % HP;
    t /= HP;
    int cq = t % NCQ;
    int b  = t / NCQ;
    int w  = wq * 4;
    int h  = hp * 2;                 // output rows h, h+1

    // ---- filter taps for both output rows (pixels w..w+3) ----
    const float* fp0 = f + (size_t)b * 9 * HW + (size_t)h * W + w;
    float4 fv0[9], fv1[9];
#pragma unroll
    for (int i = 0; i < 9; ++i) {
        fv0[i] = *(const float4*)(fp0 + (size_t)i * HW);        // row h
        fv1[i] = *(const float4*)(fp0 + (size_t)i * HW + W);    // row h+1
    }

    // vertical boundaries: top taps of row 0, bottom taps of row H-1
    if (hp == 0) {
#pragma unroll
        for (int i = 0; i < 3; ++i) fv0[i] = make_float4(0.f, 0.f, 0.f, 0.f);
    }
    if (hp == HP - 1) {
#pragma unroll
        for (int i = 6; i < 9; ++i) fv1[i] = make_float4(0.f, 0.f, 0.f, 0.f);
    }
    // horizontal boundaries
    if (w == 0) {
        fv0[0].x = 0.f; fv0[3].x = 0.f; fv0[6].x = 0.f;
        fv1[0].x = 0.f; fv1[3].x = 0.f; fv1[6].x = 0.f;
    }
    if (w == W - 4) {
        fv0[2].w = 0.f; fv0[5].w = 0.f; fv0[8].w = 0.f;
        fv1[2].w = 0.f; fv1[5].w = 0.f; fv1[8].w = 0.f;
    }

    // input rows h-1 .. h+2, clamped (dead loads in-bounds, filter zeroed)
    int roff[4];
    roff[0] = (hp > 0)      ? -W    : 0;     // row h-1
    roff[1] = 0;                              // row h
    roff[2] = W;                              // row h+1
    roff[3] = (hp < HP - 1) ? 2 * W : W;     // row h+2
    int offm1 = (w > 0)     ? -1 : 0;        // column w-1
    int offp4 = (w + 4 < W) ?  4 : 3;        // column w+4

    const float* xp = x   + ((size_t)b * C + cq * CCH) * HW + (size_t)h * W + w;
    float*       op = out + ((size_t)b * C + cq * CCH) * HW + (size_t)h * W + w;

    for (int c = 0; c < CCH; ++c) {
        const float* xc = xp + (size_t)c * HW;

        // 12 independent loads covering 4 input rows
        float4 m[4];
        float  vm[4], vp[4];
#pragma unroll
        for (int r = 0; r < 4; ++r) {
            const float* row = xc + roff[r];
            m[r]  = *(const float4*)row;     // columns w..w+3
            vm[r] = __ldg(row + offm1);      // column w-1
            vp[r] = __ldg(row + offp4);      // column w+4
        }

        // output row h: input rows 0,1,2
        float a0 = 0.f, a1 = 0.f, a2 = 0.f, a3 = 0.f;
#pragma unroll
        for (int j = 0; j < 3; ++j) {
            float4 F0 = fv0[3 * j + 0], F1 = fv0[3 * j + 1], F2 = fv0[3 * j + 2];
            float4 mm = m[j]; float vml = vm[j], vpr = vp[j];
            a0 = fmaf(vml,  F0.x, a0); a0 = fmaf(mm.x, F1.x, a0); a0 = fmaf(mm.y, F2.x, a0);
            a1 = fmaf(mm.x, F0.y, a1); a1 = fmaf(mm.y, F1.y, a1); a1 = fmaf(mm.z, F2.y, a1);
            a2 = fmaf(mm.y, F0.z, a2); a2 = fmaf(mm.z, F1.z, a2); a2 = fmaf(mm.w, F2.z, a2);
            a3 = fmaf(mm.z, F0.w, a3); a3 = fmaf(mm.w, F1.w, a3); a3 = fmaf(vpr,  F2.w, a3);
        }
        // output row h+1: input rows 1,2,3
        float b0 = 0.f, b1 = 0.f, b2 = 0.f, b3 = 0.f;
#pragma unroll
        for (int j = 0; j < 3; ++j) {
            float4 F0 = fv1[3 * j + 0], F1 = fv1[3 * j + 1], F2 = fv1[3 * j + 2];
            float4 mm = m[j + 1]; float vml = vm[j + 1], vpr = vp[j + 1];
            b0 = fmaf(vml,  F0.x, b0); b0 = fmaf(mm.x, F1.x, b0); b0 = fmaf(mm.y, F2.x, b0);
            b1 = fmaf(mm.x, F0.y, b1); b1 = fmaf(mm.y, F1.y, b1); b1 = fmaf(mm.z, F2.y, b1);
            b2 = fmaf(mm.y, F0.z, b2); b2 = fmaf(mm.z, F1.z, b2); b2 = fmaf(mm.w, F2.z, b2);
            b3 = fmaf(mm.z, F0.w, b3); b3 = fmaf(mm.w, F1.w, b3); b3 = fmaf(vpr,  F2.w, b3);
        }

        float* oc = op + (size_t)c * HW;
        *(float4*)oc       = make_float4(a0, a1, a2, a3);
        *(float4*)(oc + W) = make_float4(b0, b1, b2, b3);
    }
}

extern "C" void kernel_launch(void* const* d_in, const int* in_sizes, int n_in,
                              void* d_out, int out_size)
{
    const float* x = (const float*)d_in[0];   // [4,128,180,320]
    const float* f = (const float*)d_in[1];   // [4,9,180,320]
    float* out = (float*)d_out;               // [4,128,180,320]

    duf_kernel<<<GRID, THREADS>>>(x, f, out);
}

// round 7
// speedup vs baseline: 1.9988x; 1.0846x over previous
#include <cuda_runtime.h>

// DynamicUpsamplingFilter: out[b,c,h,w] = sum_{dy,dx} x_pad[b,c,h+dy,w+dx] * filters[b,dy*3+dx,h,w]
// x: [4,128,180,320] f32, filters: [4,9,180,320] f32, out: [4,128,180,320] f32.
//
// R7 = R6 (4w x 2h tile, 16 channels/thread; best 57.8us) + MLP boost.
// R6 was latency-limited (DRAM 50%, L1 50%, occ 24%, issue 24%, nothing
// saturated). Channel loop unrolled x2 with all 24 loads of both
// sub-iterations issued before the FMAs -> ~50% more loads in flight per SM.
// 128-thread blocks, launch_bounds(128,3): 170-reg budget, est. need ~140,
// no spills (the R4 failure mode was a forced 85-reg cap).

constexpr int B = 4, C = 128, H = 180, W = 320;
constexpr int HW = H * W;
constexpr int WQ = W / 4;            // 80 pixel-quads per row
constexpr int HP = H / 2;            // 90 row-pairs
constexpr int CCH = 16;              // channels per thread
constexpr int NCQ = C / CCH;         // 8 channel-groups
constexpr int THREADS = 128;
constexpr int NTHREADS_TOTAL = B * NCQ * HP * WQ;  // 230400
constexpr int GRID = NTHREADS_TOTAL / THREADS;     // 1800

__global__ __launch_bounds__(THREADS, 3)
void duf_kernel(const float* __restrict__ x,
                const float* __restrict__ f,
                float* __restrict__ out)
{
    int idx = blockIdx.x * THREADS + threadIdx.x;

    // consecutive threads -> consecutive wq for coalescing
    int wq = idx % WQ;
    int t  = idx / WQ;
    int hp = t % HP;
    t /= HP;
    int cq = t % NCQ;
    int b  = t / NCQ;
    int w  = wq * 4;
    int h  = hp * 2;                 // output rows h, h+1

    // ---- filter taps for both output rows (pixels w..w+3) ----
    const float* fp0 = f + (size_t)b * 9 * HW + (size_t)h * W + w;
    float4 fv0[9], fv1[9];
#pragma unroll
    for (int i = 0; i < 9; ++i) {
        fv0[i] = *(const float4*)(fp0 + (size_t)i * HW);        // row h
        fv1[i] = *(const float4*)(fp0 + (size_t)i * HW + W);    // row h+1
    }

    // vertical boundaries
    if (hp == 0) {
#pragma unroll
        for (int i = 0; i < 3; ++i) fv0[i] = make_float4(0.f, 0.f, 0.f, 0.f);
    }
    if (hp == HP - 1) {
#pragma unroll
        for (int i = 6; i < 9; ++i) fv1[i] = make_float4(0.f, 0.f, 0.f, 0.f);
    }
    // horizontal boundaries
    if (w == 0) {
        fv0[0].x = 0.f; fv0[3].x = 0.f; fv0[6].x = 0.f;
        fv1[0].x = 0.f; fv1[3].x = 0.f; fv1[6].x = 0.f;
    }
    if (w == W - 4) {
        fv0[2].w = 0.f; fv0[5].w = 0.f; fv0[8].w = 0.f;
        fv1[2].w = 0.f; fv1[5].w = 0.f; fv1[8].w = 0.f;
    }

    // input rows h-1 .. h+2, clamped (dead loads in-bounds, filter zeroed)
    int roff[4];
    roff[0] = (hp > 0)      ? -W    : 0;     // row h-1
    roff[1] = 0;                              // row h
    roff[2] = W;                              // row h+1
    roff[3] = (hp < HP - 1) ? 2 * W : W;     // row h+2
    int offm1 = (w > 0)     ? -1 : 0;        // column w-1
    int offp4 = (w + 4 < W) ?  4 : 3;        // column w+4

    const float* xp = x   + ((size_t)b * C + cq * CCH) * HW + (size_t)h * W + w;
    float*       op = out + ((size_t)b * C + cq * CCH) * HW + (size_t)h * W + w;

    for (int c = 0; c < CCH; c += 2) {
        // ---- issue ALL loads for two channels up front (24 independent) ----
        float4 m[2][4];
        float  vm[2][4], vp[2][4];
#pragma unroll
        for (int u = 0; u < 2; ++u) {
            const float* xc = xp + (size_t)(c + u) * HW;
#pragma unroll
            for (int r = 0; r < 4; ++r) {
                const float* row = xc + roff[r];
                m[u][r]  = *(const float4*)row;   // columns w..w+3
                vm[u][r] = __ldg(row + offm1);    // column w-1
                vp[u][r] = __ldg(row + offp4);    // column w+4
            }
        }

#pragma unroll
        for (int u = 0; u < 2; ++u) {
            // output row h: input rows 0,1,2
            float a0 = 0.f, a1 = 0.f, a2 = 0.f, a3 = 0.f;
#pragma unroll
            for (int j = 0; j < 3; ++j) {
                float4 F0 = fv0[3 * j + 0], F1 = fv0[3 * j + 1], F2 = fv0[3 * j + 2];
                float4 mm = m[u][j]; float vml = vm[u][j], vpr = vp[u][j];
                a0 = fmaf(vml,  F0.x, a0); a0 = fmaf(mm.x, F1.x, a0); a0 = fmaf(mm.y, F2.x, a0);
                a1 = fmaf(mm.x, F0.y, a1); a1 = fmaf(mm.y, F1.y, a1); a1 = fmaf(mm.z, F2.y, a1);
                a2 = fmaf(mm.y, F0.z, a2); a2 = fmaf(mm.z, F1.z, a2); a2 = fmaf(mm.w, F2.z, a2);
                a3 = fmaf(mm.z, F0.w, a3); a3 = fmaf(mm.w, F1.w, a3); a3 = fmaf(vpr,  F2.w, a3);
            }
            // output row h+1: input rows 1,2,3
            float b0 = 0.f, b1 = 0.f, b2 = 0.f, b3 = 0.f;
#pragma unroll
            for (int j = 0; j < 3; ++j) {
                float4 F0 = fv1[3 * j + 0], F1 = fv1[3 * j + 1], F2 = fv1[3 * j + 2];
                float4 mm = m[u][j + 1]; float vml = vm[u][j + 1], vpr = vp[u][j + 1];
                b0 = fmaf(vml,  F0.x, b0); b0 = fmaf(mm.x, F1.x, b0); b0 = fmaf(mm.y, F2.x, b0);
                b1 = fmaf(mm.x, F0.y, b1); b1 = fmaf(mm.y, F1.y, b1); b1 = fmaf(mm.z, F2.y, b1);
                b2 = fmaf(mm.y, F0.z, b2); b2 = fmaf(mm.z, F1.z, b2); b2 = fmaf(mm.w, F2.z, b2);
                b3 = fmaf(mm.z, F0.w, b3); b3 = fmaf(mm.w, F1.w, b3); b3 = fmaf(vpr,  F2.w, b3);
            }

            float* oc = op + (size_t)(c + u) * HW;
            *(float4*)oc       = make_float4(a0, a1, a2, a3);
            *(float4*)(oc + W) = make_float4(b0, b1, b2, b3);
        }
    }
}

extern "C" void kernel_launch(void* const* d_in, const int* in_sizes, int n_in,
                              void* d_out, int out_size)
{
    const float* x = (const float*)d_in[0];   // [4,128,180,320]
    const float* f = (const float*)d_in[1];   // [4,9,180,320]
    float* out = (float*)d_out;               // [4,128,180,320]

    duf_kernel<<<GRID, THREADS>>>(x, f, out);
}